// round 2
// baseline (speedup 1.0000x reference)
#include <cuda_runtime.h>
#include <cuda_bf16.h>
#include <math.h>

#define N_NODES 50000
#define N_EDGES 800000
#define IN_C 128
#define HID_C 128
#define OUT_C 64

// ---------------- scratch (static device globals; no allocation) ----------------
__device__ int   g_is64;
__device__ int   g_src[N_EDGES];
__device__ int   g_dst[N_EDGES];
__device__ int   g_edeg[N_NODES];
__device__ float g_dinv[N_NODES];
__device__ int   g_rowptr[N_NODES + 1];
__device__ int   g_cursor[N_NODES];
__device__ int   g_col[N_EDGES];
__device__ float g_wedge[N_EDGES];

__device__ float g_aggx[N_NODES * 128];   // A_hat @ x
__device__ float g_bufA[N_NODES * 256];   // [h_s1 | h2a]
__device__ float g_bufB[N_NODES * 256];   // A_hat @ bufA
__device__ float g_h1[N_NODES * 128];
__device__ float g_h2[N_NODES * 128];
__device__ float g_comb[N_NODES * 256];   // [h_struct | h_meta]

// ---------------- edge dtype probe + extraction ----------------
// If the buffer is int64 (little-endian, values < 50000), every odd int32 word
// in the first 4096 words is 0. If int32, those words are random node indices.
__global__ void k_detect(const int* __restrict__ ei32) {
    __shared__ int nz;
    if (threadIdx.x == 0) nz = 0;
    __syncthreads();
    int local = 0;
    for (int i = threadIdx.x; i < 2048; i += blockDim.x)
        if (ei32[2 * i + 1] != 0) local = 1;
    if (local) atomicOr(&nz, 1);
    __syncthreads();
    if (threadIdx.x == 0) g_is64 = nz ? 0 : 1;
}

__global__ void k_extract(const int* __restrict__ ei32) {
    int e = blockIdx.x * blockDim.x + threadIdx.x;
    if (e < N_EDGES) {
        int s, d;
        if (g_is64) {
            s = ei32[2 * e];
            d = ei32[2 * (N_EDGES + e)];
        } else {
            s = ei32[e];
            d = ei32[N_EDGES + e];
        }
        g_src[e] = s;
        g_dst[e] = d;
    }
}

// ---------------- CSR build ----------------
__global__ void k_init_deg() {
    int i = blockIdx.x * blockDim.x + threadIdx.x;
    if (i < N_NODES) g_edeg[i] = 0;
}

__global__ void k_count() {
    int e = blockIdx.x * blockDim.x + threadIdx.x;
    if (e < N_EDGES) atomicAdd(&g_edeg[g_dst[e]], 1);
}

__global__ void k_dinv() {
    int i = blockIdx.x * blockDim.x + threadIdx.x;
    if (i < N_NODES) g_dinv[i] = rsqrtf((float)(g_edeg[i] + 1));  // +1 self loop
}

// single-block exclusive scan of g_edeg -> g_rowptr / g_cursor
__global__ void k_scan() {
    __shared__ int part[1024];
    const int t = threadIdx.x;
    const int CH = (N_NODES + 1023) / 1024;  // 49
    int start = t * CH;
    int s = 0;
    for (int i = 0; i < CH; i++) {
        int idx = start + i;
        if (idx < N_NODES) s += g_edeg[idx];
    }
    part[t] = s;
    __syncthreads();
    for (int off = 1; off < 1024; off <<= 1) {
        int v = (t >= off) ? part[t - off] : 0;
        __syncthreads();
        part[t] += v;
        __syncthreads();
    }
    int run = (t == 0) ? 0 : part[t - 1];
    for (int i = 0; i < CH; i++) {
        int idx = start + i;
        if (idx < N_NODES) {
            g_rowptr[idx] = run;
            g_cursor[idx] = run;
            run += g_edeg[idx];
        }
    }
    if (t == 1023) g_rowptr[N_NODES] = run;
}

__global__ void k_fill() {
    int e = blockIdx.x * blockDim.x + threadIdx.x;
    if (e < N_EDGES) {
        int s = g_src[e];
        int d = g_dst[e];
        int p = atomicAdd(&g_cursor[d], 1);
        g_col[p] = s;
        g_wedge[p] = g_dinv[s] * g_dinv[d];
    }
}

// ---------------- normalized aggregation: out = A_hat @ in (C channels) ----------------
template <int C>
__global__ void k_agg(const float* __restrict__ in, float* __restrict__ out) {
    int n = blockIdx.x;
    int c = threadIdx.x;
    float dn = g_dinv[n];
    float acc = dn * dn * in[n * C + c];  // self loop
    int j = g_rowptr[n];
    int end = g_rowptr[n + 1];
    for (; j + 1 < end; j += 2) {
        int s0 = g_col[j];
        int s1 = g_col[j + 1];
        float w0 = g_wedge[j];
        float w1 = g_wedge[j + 1];
        acc += w0 * in[s0 * C + c];
        acc += w1 * in[s1 * C + c];
    }
    if (j < end) {
        acc += g_wedge[j] * in[g_col[j] * C + c];
    }
    out[n * C + c] = acc;
}

// ---------------- tiled fp32 GEMM: C = [relu](A @ W + bias) ----------------
#define BM 64
#define BN 64
#define BK 16
__global__ void k_gemm(const float* __restrict__ A, int lda,
                       const float* __restrict__ W, int ldw,
                       const float* __restrict__ bias,
                       float* __restrict__ Cout, int ldc,
                       int Mrows, int K, int do_relu) {
    __shared__ float As[BK][BM];
    __shared__ float Ws[BK][BN];

    const int bm = blockIdx.y * BM;
    const int bn = blockIdx.x * BN;
    const int tid = threadIdx.x;       // 256 threads

    const int a_row = tid >> 2;          // 0..63
    const int a_k4  = (tid & 3) << 2;    // 0,4,8,12
    const int w_k  = tid >> 4;           // 0..15
    const int w_n4 = (tid & 15) << 2;    // 0..60

    const int tx = tid & 15;             // n
    const int ty = tid >> 4;             // m

    int arow_g = bm + a_row;
    if (arow_g >= Mrows) arow_g = Mrows - 1;  // clamp; store is guarded
    const float* Aptr = A + (long)arow_g * lda;

    float acc[4][4];
#pragma unroll
    for (int i = 0; i < 4; i++)
#pragma unroll
        for (int jj = 0; jj < 4; jj++) acc[i][jj] = 0.0f;

    for (int k0 = 0; k0 < K; k0 += BK) {
        float4 av = *reinterpret_cast<const float4*>(Aptr + k0 + a_k4);
        As[a_k4 + 0][a_row] = av.x;
        As[a_k4 + 1][a_row] = av.y;
        As[a_k4 + 2][a_row] = av.z;
        As[a_k4 + 3][a_row] = av.w;
        float4 wv = *reinterpret_cast<const float4*>(W + (long)(k0 + w_k) * ldw + bn + w_n4);
        *reinterpret_cast<float4*>(&Ws[w_k][w_n4]) = wv;
        __syncthreads();
#pragma unroll
        for (int kk = 0; kk < BK; kk++) {
            float4 a = *reinterpret_cast<const float4*>(&As[kk][ty << 2]);
            float4 w = *reinterpret_cast<const float4*>(&Ws[kk][tx << 2]);
            acc[0][0] += a.x * w.x; acc[0][1] += a.x * w.y; acc[0][2] += a.x * w.z; acc[0][3] += a.x * w.w;
            acc[1][0] += a.y * w.x; acc[1][1] += a.y * w.y; acc[1][2] += a.y * w.z; acc[1][3] += a.y * w.w;
            acc[2][0] += a.z * w.x; acc[2][1] += a.z * w.y; acc[2][2] += a.z * w.z; acc[2][3] += a.z * w.w;
            acc[3][0] += a.w * w.x; acc[3][1] += a.w * w.y; acc[3][2] += a.w * w.z; acc[3][3] += a.w * w.w;
        }
        __syncthreads();
    }

    float b0 = bias[bn + (tx << 2) + 0];
    float b1 = bias[bn + (tx << 2) + 1];
    float b2 = bias[bn + (tx << 2) + 2];
    float b3 = bias[bn + (tx << 2) + 3];
#pragma unroll
    for (int i = 0; i < 4; i++) {
        int row = bm + (ty << 2) + i;
        if (row < Mrows) {
            float v0 = acc[i][0] + b0;
            float v1 = acc[i][1] + b1;
            float v2 = acc[i][2] + b2;
            float v3 = acc[i][3] + b3;
            if (do_relu) {
                v0 = fmaxf(v0, 0.0f); v1 = fmaxf(v1, 0.0f);
                v2 = fmaxf(v2, 0.0f); v3 = fmaxf(v3, 0.0f);
            }
            float* cp = Cout + (long)row * ldc + bn + (tx << 2);
            cp[0] = v0; cp[1] = v1; cp[2] = v2; cp[3] = v3;
        }
    }
}

// ---------------- attention fusion over 2 branches ----------------
__global__ void k_attn(const float* __restrict__ watt, const float* __restrict__ batt) {
    int n = blockIdx.x;
    int c = threadIdx.x;  // 128
    float h1v = g_h1[n * 128 + c];
    float h2v = g_h2[n * 128 + c];
    float wa = watt[c];
    float p1 = h1v * wa;
    float p2 = h2v * wa;
#pragma unroll
    for (int o = 16; o > 0; o >>= 1) {
        p1 += __shfl_down_sync(0xFFFFFFFFu, p1, o);
        p2 += __shfl_down_sync(0xFFFFFFFFu, p2, o);
    }
    __shared__ float s1[4], s2[4];
    __shared__ float a1s;
    int w = c >> 5;
    if ((c & 31) == 0) { s1[w] = p1; s2[w] = p2; }
    __syncthreads();
    if (c == 0) {
        float S1 = s1[0] + s1[1] + s1[2] + s1[3] + batt[0];
        float S2 = s2[0] + s2[1] + s2[2] + s2[3] + batt[0];
        a1s = 1.0f / (1.0f + expf(S2 - S1));   // softmax over {S1,S2}
    }
    __syncthreads();
    float a1 = a1s;
    g_comb[n * 256 + 128 + c] = a1 * h1v + (1.0f - a1) * h2v;
}

// ---------------- launch ----------------
extern "C" void kernel_launch(void* const* d_in, const int* in_sizes, int n_in,
                              void* d_out, int out_size) {
    const float* x    = (const float*)d_in[0];
    const int*   ei32 = (const int*)d_in[1];   // int32 OR int64 (probed on device)
    const float* W_s1 = (const float*)d_in[2];
    const float* b_s1 = (const float*)d_in[3];
    const float* W_s2 = (const float*)d_in[4];
    const float* b_s2 = (const float*)d_in[5];
    const float* W_m1 = (const float*)d_in[6];
    const float* b_m1 = (const float*)d_in[7];
    const float* W_m21 = (const float*)d_in[8];
    const float* b_m21 = (const float*)d_in[9];
    const float* W_m22 = (const float*)d_in[10];
    const float* b_m22 = (const float*)d_in[11];
    const float* W_att = (const float*)d_in[12];
    const float* b_att = (const float*)d_in[13];
    const float* W_fc  = (const float*)d_in[14];
    const float* b_fc  = (const float*)d_in[15];
    float* out = (float*)d_out;

    float* aggx; cudaGetSymbolAddress((void**)&aggx, g_aggx);
    float* bufA; cudaGetSymbolAddress((void**)&bufA, g_bufA);
    float* bufB; cudaGetSymbolAddress((void**)&bufB, g_bufB);
    float* h1;   cudaGetSymbolAddress((void**)&h1, g_h1);
    float* h2;   cudaGetSymbolAddress((void**)&h2, g_h2);
    float* comb; cudaGetSymbolAddress((void**)&comb, g_comb);

    const int TB = 256;
    // edge layout probe + normalize to int32 src/dst
    k_detect<<<1, 256>>>(ei32);
    k_extract<<<(N_EDGES + TB - 1) / TB, TB>>>(ei32);

    // CSR build
    k_init_deg<<<(N_NODES + TB - 1) / TB, TB>>>();
    k_count<<<(N_EDGES + TB - 1) / TB, TB>>>();
    k_dinv<<<(N_NODES + TB - 1) / TB, TB>>>();
    k_scan<<<1, 1024>>>();
    k_fill<<<(N_EDGES + TB - 1) / TB, TB>>>();

    // agg_x = A_hat @ x
    k_agg<128><<<N_NODES, 128>>>(x, aggx);

    dim3 blk(256);
    dim3 g2x782(2, (N_NODES + BM - 1) / BM);
    dim3 g1x782(1, (N_NODES + BM - 1) / BM);

    // layer-1 convs share agg_x
    k_gemm<<<g2x782, blk>>>(aggx, 128, W_s1, 128, b_s1, bufA, 256, N_NODES, 128, 1);        // h_s1
    k_gemm<<<g2x782, blk>>>(aggx, 128, W_m21, 128, b_m21, bufA + 128, 256, N_NODES, 128, 1);// h2a
    k_gemm<<<g2x782, blk>>>(aggx, 128, W_m1, 128, b_m1, h1, 128, N_NODES, 128, 1);          // h1

    // layer-2 shared aggregation over [h_s1 | h2a]
    k_agg<256><<<N_NODES, 256>>>(bufA, bufB);

    k_gemm<<<g2x782, blk>>>(bufB, 256, W_s2, 128, b_s2, comb, 256, N_NODES, 128, 1);        // h_struct
    k_gemm<<<g2x782, blk>>>(bufB + 128, 256, W_m22, 128, b_m22, h2, 128, N_NODES, 128, 1);  // h2

    // attention fusion -> comb[:, 128:]
    k_attn<<<N_NODES, 128>>>(W_att, b_att);

    // final FC: [N,256] @ [256,64]
    k_gemm<<<g1x782, blk>>>(comb, 256, W_fc, 64, b_fc, out, 64, N_NODES, 256, 0);

    (void)in_sizes; (void)n_in; (void)out_size;
}

// round 3
// speedup vs baseline: 1.0912x; 1.0912x over previous
#include <cuda_runtime.h>
#include <cuda_bf16.h>
#include <math.h>

#define N_NODES 50000
#define N_EDGES 800000

// ---------------- scratch (static device globals; no allocation) ----------------
__device__ int   g_is64;
__device__ int   g_src[N_EDGES];
__device__ int   g_dst[N_EDGES];
__device__ int   g_edeg[N_NODES];
__device__ float g_dinv[N_NODES];
__device__ int   g_rowptr[N_NODES + 1];
__device__ int   g_cursor[N_NODES];
__device__ int   g_col[N_EDGES];
__device__ float g_wedge[N_EDGES];

__device__ float g_aggx[N_NODES * 128];   // A_hat @ x
__device__ float g_bufA[N_NODES * 256];   // [h_s1 | h2a]
__device__ float g_bufB[N_NODES * 256];   // A_hat @ bufA
__device__ float g_h1[N_NODES * 128];
__device__ float g_h2[N_NODES * 128];
__device__ float g_comb[N_NODES * 256];   // [h_struct | h_meta]

// ---------------- edge dtype probe + extraction ----------------
__global__ void k_detect(const int* __restrict__ ei32) {
    __shared__ int nz;
    if (threadIdx.x == 0) nz = 0;
    __syncthreads();
    int local = 0;
    for (int i = threadIdx.x; i < 2048; i += blockDim.x)
        if (ei32[2 * i + 1] != 0) local = 1;
    if (local) atomicOr(&nz, 1);
    __syncthreads();
    if (threadIdx.x == 0) g_is64 = nz ? 0 : 1;
}

__global__ void k_extract(const int* __restrict__ ei32) {
    int e = blockIdx.x * blockDim.x + threadIdx.x;
    if (e < N_EDGES) {
        int s, d;
        if (g_is64) {
            s = ei32[2 * e];
            d = ei32[2 * (N_EDGES + e)];
        } else {
            s = ei32[e];
            d = ei32[N_EDGES + e];
        }
        g_src[e] = s;
        g_dst[e] = d;
    }
}

// ---------------- CSR build ----------------
__global__ void k_init_deg() {
    int i = blockIdx.x * blockDim.x + threadIdx.x;
    if (i < N_NODES) g_edeg[i] = 0;
}

__global__ void k_count() {
    int e = blockIdx.x * blockDim.x + threadIdx.x;
    if (e < N_EDGES) atomicAdd(&g_edeg[g_dst[e]], 1);
}

__global__ void k_dinv() {
    int i = blockIdx.x * blockDim.x + threadIdx.x;
    if (i < N_NODES) g_dinv[i] = rsqrtf((float)(g_edeg[i] + 1));
}

__global__ void k_scan() {
    __shared__ int part[1024];
    const int t = threadIdx.x;
    const int CH = (N_NODES + 1023) / 1024;
    int start = t * CH;
    int s = 0;
    for (int i = 0; i < CH; i++) {
        int idx = start + i;
        if (idx < N_NODES) s += g_edeg[idx];
    }
    part[t] = s;
    __syncthreads();
    for (int off = 1; off < 1024; off <<= 1) {
        int v = (t >= off) ? part[t - off] : 0;
        __syncthreads();
        part[t] += v;
        __syncthreads();
    }
    int run = (t == 0) ? 0 : part[t - 1];
    for (int i = 0; i < CH; i++) {
        int idx = start + i;
        if (idx < N_NODES) {
            g_rowptr[idx] = run;
            g_cursor[idx] = run;
            run += g_edeg[idx];
        }
    }
    if (t == 1023) g_rowptr[N_NODES] = run;
}

__global__ void k_fill() {
    int e = blockIdx.x * blockDim.x + threadIdx.x;
    if (e < N_EDGES) {
        int s = g_src[e];
        int d = g_dst[e];
        int p = atomicAdd(&g_cursor[d], 1);
        g_col[p] = s;
        g_wedge[p] = g_dinv[s] * g_dinv[d];
    }
}

// ---------------- normalized aggregation: out = A_hat @ in (C channels) ----------------
template <int C>
__global__ void k_agg(const float* __restrict__ in, float* __restrict__ out) {
    int n = blockIdx.x;
    int c = threadIdx.x;
    float dn = g_dinv[n];
    float acc = dn * dn * in[n * C + c];  // self loop
    int j = g_rowptr[n];
    int end = g_rowptr[n + 1];
    for (; j + 1 < end; j += 2) {
        int s0 = g_col[j];
        int s1 = g_col[j + 1];
        float w0 = g_wedge[j];
        float w1 = g_wedge[j + 1];
        acc += w0 * in[s0 * C + c];
        acc += w1 * in[s1 * C + c];
    }
    if (j < end) {
        acc += g_wedge[j] * in[g_col[j] * C + c];
    }
    out[n * C + c] = acc;
}

// ---------------- packed-f32x2 GEMM ----------------
__device__ __forceinline__ unsigned long long pack2(float v) {
    unsigned long long r;
    asm("mov.b64 %0, {%1, %1};" : "=l"(r) : "f"(v));
    return r;
}
__device__ __forceinline__ void ffma2(unsigned long long& acc,
                                      unsigned long long a,
                                      unsigned long long b) {
    asm("fma.rn.f32x2 %0, %1, %2, %0;" : "+l"(acc) : "l"(a), "l"(b));
}
__device__ __forceinline__ void unpack2(unsigned long long v, float& lo, float& hi) {
    asm("mov.b64 {%0, %1}, %2;" : "=f"(lo), "=f"(hi) : "l"(v));
}

struct Jobs {
    const float* A[3];
    const float* W[3];
    const float* bias[3];
    float*       C[3];
    int lda[3];
    int ldw[3];
    int ldc[3];
};

// C = [relu](A @ W + bias); BM=128, BN=16*TN, BK=16, 256 threads,
// micro-tile 8m x TNn per thread. m-pairs load packed from smem; w broadcasts packed.
template <int TN>
__global__ __launch_bounds__(256, 2) void k_gemm2(Jobs jobs, int Mrows, int K, int do_relu) {
    constexpr int BM = 128;
    constexpr int BN = 16 * TN;
    constexpr int BK = 16;

    __shared__ float As[BK][BM];
    __shared__ float Ws[BK][BN];

    const int job = blockIdx.z;
    const float* A    = jobs.A[job];
    const float* W    = jobs.W[job];
    const float* bias = jobs.bias[job];
    float*       Cout = jobs.C[job];
    const int lda = jobs.lda[job];
    const int ldw = jobs.ldw[job];
    const int ldc = jobs.ldc[job];

    const int tid = threadIdx.x;
    const int bm = blockIdx.y * BM;
    const int bn = blockIdx.x * BN;

    // A loader: each thread loads row (tid>>1), k-span ((tid&1)*8 .. +7) as 2 float4
    const int a_row = tid >> 1;
    const int a_k8  = (tid & 1) * 8;
    int arow_g = bm + a_row;
    if (arow_g >= Mrows) arow_g = Mrows - 1;
    const float* Ap = A + (long)arow_g * lda + a_k8;

    // W loader
    const int w_k = tid >> 4;
    const int w_n = (tid & 15) * (TN == 8 ? 8 : 4);

    const int tx = tid & 15;   // n group
    const int ty = tid >> 4;   // m group

    unsigned long long acc[4][TN];
#pragma unroll
    for (int i = 0; i < 4; i++)
#pragma unroll
        for (int j = 0; j < TN; j++) acc[i][j] = 0ULL;

    for (int k0 = 0; k0 < K; k0 += BK) {
        float4 av0 = *reinterpret_cast<const float4*>(Ap + k0);
        float4 av1 = *reinterpret_cast<const float4*>(Ap + k0 + 4);
        As[a_k8 + 0][a_row] = av0.x;
        As[a_k8 + 1][a_row] = av0.y;
        As[a_k8 + 2][a_row] = av0.z;
        As[a_k8 + 3][a_row] = av0.w;
        As[a_k8 + 4][a_row] = av1.x;
        As[a_k8 + 5][a_row] = av1.y;
        As[a_k8 + 6][a_row] = av1.z;
        As[a_k8 + 7][a_row] = av1.w;

        const float* Wp = W + (long)(k0 + w_k) * ldw + bn + w_n;
        if (TN == 8) {
            float4 wv0 = *reinterpret_cast<const float4*>(Wp);
            float4 wv1 = *reinterpret_cast<const float4*>(Wp + 4);
            *reinterpret_cast<float4*>(&Ws[w_k][w_n]) = wv0;
            *reinterpret_cast<float4*>(&Ws[w_k][w_n + 4]) = wv1;
        } else {
            float4 wv0 = *reinterpret_cast<const float4*>(Wp);
            *reinterpret_cast<float4*>(&Ws[w_k][w_n]) = wv0;
        }
        __syncthreads();

#pragma unroll
        for (int kk = 0; kk < BK; kk++) {
            // 8 m-values as 4 packed f32x2 (naturally contiguous in As)
            ulonglong2 am0 = *reinterpret_cast<const ulonglong2*>(&As[kk][ty * 8]);
            ulonglong2 am1 = *reinterpret_cast<const ulonglong2*>(&As[kk][ty * 8 + 4]);
            unsigned long long a2[4] = {am0.x, am0.y, am1.x, am1.y};

            float wv[TN];
            float4 wf0 = *reinterpret_cast<const float4*>(&Ws[kk][tx * TN]);
            wv[0] = wf0.x; wv[1] = wf0.y; wv[2] = wf0.z; wv[3] = wf0.w;
            if (TN == 8) {
                float4 wf1 = *reinterpret_cast<const float4*>(&Ws[kk][tx * TN + 4]);
                wv[4] = wf1.x; wv[5] = wf1.y; wv[6] = wf1.z; wv[7] = wf1.w;
            }

            unsigned long long wb[TN];
#pragma unroll
            for (int j = 0; j < TN; j++) wb[j] = pack2(wv[j]);

#pragma unroll
            for (int mp = 0; mp < 4; mp++)
#pragma unroll
                for (int j = 0; j < TN; j++) ffma2(acc[mp][j], a2[mp], wb[j]);
        }
        __syncthreads();
    }

    // epilogue
    float bv[TN];
#pragma unroll
    for (int j = 0; j < TN; j++) bv[j] = bias[bn + tx * TN + j];

#pragma unroll
    for (int mp = 0; mp < 4; mp++) {
        int row0 = bm + ty * 8 + 2 * mp;
        int row1 = row0 + 1;
        float r0[TN], r1[TN];
#pragma unroll
        for (int j = 0; j < TN; j++) {
            float lo, hi;
            unpack2(acc[mp][j], lo, hi);
            lo += bv[j];
            hi += bv[j];
            if (do_relu) { lo = fmaxf(lo, 0.0f); hi = fmaxf(hi, 0.0f); }
            r0[j] = lo; r1[j] = hi;
        }
        if (row0 < Mrows) {
            float* cp = Cout + (long)row0 * ldc + bn + tx * TN;
#pragma unroll
            for (int j = 0; j < TN; j += 4)
                *reinterpret_cast<float4*>(cp + j) = make_float4(r0[j], r0[j+1], r0[j+2], r0[j+3]);
        }
        if (row1 < Mrows) {
            float* cp = Cout + (long)row1 * ldc + bn + tx * TN;
#pragma unroll
            for (int j = 0; j < TN; j += 4)
                *reinterpret_cast<float4*>(cp + j) = make_float4(r1[j], r1[j+1], r1[j+2], r1[j+3]);
        }
    }
}

// ---------------- attention fusion over 2 branches ----------------
__global__ void k_attn(const float* __restrict__ watt, const float* __restrict__ batt) {
    int n = blockIdx.x;
    int c = threadIdx.x;  // 128
    float h1v = g_h1[n * 128 + c];
    float h2v = g_h2[n * 128 + c];
    float wa = watt[c];
    float p1 = h1v * wa;
    float p2 = h2v * wa;
#pragma unroll
    for (int o = 16; o > 0; o >>= 1) {
        p1 += __shfl_down_sync(0xFFFFFFFFu, p1, o);
        p2 += __shfl_down_sync(0xFFFFFFFFu, p2, o);
    }
    __shared__ float s1[4], s2[4];
    __shared__ float a1s;
    int w = c >> 5;
    if ((c & 31) == 0) { s1[w] = p1; s2[w] = p2; }
    __syncthreads();
    if (c == 0) {
        float S1 = s1[0] + s1[1] + s1[2] + s1[3] + batt[0];
        float S2 = s2[0] + s2[1] + s2[2] + s2[3] + batt[0];
        a1s = 1.0f / (1.0f + expf(S2 - S1));
    }
    __syncthreads();
    float a1 = a1s;
    g_comb[n * 256 + 128 + c] = a1 * h1v + (1.0f - a1) * h2v;
}

// ---------------- launch ----------------
extern "C" void kernel_launch(void* const* d_in, const int* in_sizes, int n_in,
                              void* d_out, int out_size) {
    const float* x    = (const float*)d_in[0];
    const int*   ei32 = (const int*)d_in[1];
    const float* W_s1 = (const float*)d_in[2];
    const float* b_s1 = (const float*)d_in[3];
    const float* W_s2 = (const float*)d_in[4];
    const float* b_s2 = (const float*)d_in[5];
    const float* W_m1 = (const float*)d_in[6];
    const float* b_m1 = (const float*)d_in[7];
    const float* W_m21 = (const float*)d_in[8];
    const float* b_m21 = (const float*)d_in[9];
    const float* W_m22 = (const float*)d_in[10];
    const float* b_m22 = (const float*)d_in[11];
    const float* W_att = (const float*)d_in[12];
    const float* b_att = (const float*)d_in[13];
    const float* W_fc  = (const float*)d_in[14];
    const float* b_fc  = (const float*)d_in[15];
    float* out = (float*)d_out;

    float* aggx; cudaGetSymbolAddress((void**)&aggx, g_aggx);
    float* bufA; cudaGetSymbolAddress((void**)&bufA, g_bufA);
    float* bufB; cudaGetSymbolAddress((void**)&bufB, g_bufB);
    float* h1;   cudaGetSymbolAddress((void**)&h1, g_h1);
    float* h2;   cudaGetSymbolAddress((void**)&h2, g_h2);
    float* comb; cudaGetSymbolAddress((void**)&comb, g_comb);

    const int TB = 256;
    k_detect<<<1, 256>>>(ei32);
    k_extract<<<(N_EDGES + TB - 1) / TB, TB>>>(ei32);

    k_init_deg<<<(N_NODES + TB - 1) / TB, TB>>>();
    k_count<<<(N_EDGES + TB - 1) / TB, TB>>>();
    k_dinv<<<(N_NODES + TB - 1) / TB, TB>>>();
    k_scan<<<1, 1024>>>();
    k_fill<<<(N_EDGES + TB - 1) / TB, TB>>>();

    // agg_x = A_hat @ x
    k_agg<128><<<N_NODES, 128>>>(x, aggx);

    const int MB = (N_NODES + 127) / 128;  // 391

    // layer-1: three GEMMs share agg_x, one launch
    {
        Jobs j = {};
        j.A[0] = aggx;  j.W[0] = W_s1;  j.bias[0] = b_s1;  j.C[0] = bufA;        j.lda[0] = 128; j.ldw[0] = 128; j.ldc[0] = 256;
        j.A[1] = aggx;  j.W[1] = W_m21; j.bias[1] = b_m21; j.C[1] = bufA + 128;  j.lda[1] = 128; j.ldw[1] = 128; j.ldc[1] = 256;
        j.A[2] = aggx;  j.W[2] = W_m1;  j.bias[2] = b_m1;  j.C[2] = h1;          j.lda[2] = 128; j.ldw[2] = 128; j.ldc[2] = 128;
        k_gemm2<8><<<dim3(1, MB, 3), 256>>>(j, N_NODES, 128, 1);
    }

    // layer-2 shared aggregation over [h_s1 | h2a]
    k_agg<256><<<N_NODES, 256>>>(bufA, bufB);

    // layer-2: two GEMMs in one launch
    {
        Jobs j = {};
        j.A[0] = bufB;        j.W[0] = W_s2;  j.bias[0] = b_s2;  j.C[0] = comb; j.lda[0] = 256; j.ldw[0] = 128; j.ldc[0] = 256;
        j.A[1] = bufB + 128;  j.W[1] = W_m22; j.bias[1] = b_m22; j.C[1] = h2;   j.lda[1] = 256; j.ldw[1] = 128; j.ldc[1] = 128;
        j.A[2] = j.A[0];      j.W[2] = j.W[0]; j.bias[2] = j.bias[0]; j.C[2] = j.C[0]; j.lda[2] = 256; j.ldw[2] = 128; j.ldc[2] = 256;
        k_gemm2<8><<<dim3(1, MB, 2), 256>>>(j, N_NODES, 128, 1);
    }

    // attention fusion -> comb[:, 128:]
    k_attn<<<N_NODES, 128>>>(W_att, b_att);

    // final FC: [N,256] @ [256,64]
    {
        Jobs j = {};
        j.A[0] = comb; j.W[0] = W_fc; j.bias[0] = b_fc; j.C[0] = out; j.lda[0] = 256; j.ldw[0] = 64; j.ldc[0] = 64;
        j.A[1] = j.A[0]; j.W[1] = j.W[0]; j.bias[1] = j.bias[0]; j.C[1] = j.C[0]; j.lda[1] = 256; j.ldw[1] = 64; j.ldc[1] = 64;
        j.A[2] = j.A[0]; j.W[2] = j.W[0]; j.bias[2] = j.bias[0]; j.C[2] = j.C[0]; j.lda[2] = 256; j.ldw[2] = 64; j.ldc[2] = 64;
        k_gemm2<4><<<dim3(1, MB, 1), 256>>>(j, N_NODES, 256, 0);
    }

    (void)in_sizes; (void)n_in; (void)out_size;
}